// round 13
// baseline (speedup 1.0000x reference)
#include <cuda_runtime.h>
#include <cuda_fp16.h>

// Problem:
//   input   [64, 32, 32, 16, 16] f32  -> A rows [b*32+q][d], d = cl*256+hw
//   context [64, 256, 128]       f32
//   W       [8192, 256]          f32
// Outputs: wc [64,32,32,16,16] f32 (16.7M) ; attnT [64,128,32] f32 (262K)
//
// fp16 2-split (h+l), 3 MMA passes (hh, hl, lh), m16n8k16.
// k-dim in 16-groups, chunk order {k0,k1,k8,k9|k2,k3,k10,k11|...}, two 16B
// subs per row. R13: occupancy play — 64x128 CTA tiles, warp tile 32x32,
// acc=32 regs/thread, launch_bounds(256,3) -> 24 warps/SM (was 16).

#define B_SZ   64
#define IDF_SZ 8192
#define WC_ELEMS (B_SZ * IDF_SZ * 32)      // 16777216
#define W_ELEMS  (IDF_SZ * 256)
#define KS1    8
#define MROWS  (B_SZ * 32)                 // 2048
#define T2_STRIDE (MROWS * 256)            // 524288

// 64-row array: sub0 1024B | pad 64 | sub1 1024B
#define SUB64  1088
#define ARR64  2112
// 128-row array: sub0 2048B | pad 64 | sub1 2048B
#define SUB128 2112
#define ARR128 4160

#define STG      (2 * ARR64 + 2 * ARR128)  // 12544 B per stage
#define K1_SMEM  (3 * STG)                 // 37632 B
#define K1_NCH   64
#define K3_SMEM  (4 * STG)                 // 50176 B

#define CPAD  129
#define APAD2 133
#define K2_CTXF  (256 * CPAD)
#define K2_T2F   (16 * 256)
#define K2_ATTNF (16 * APAD2)
#define K2_SMEM  ((K2_CTXF + K2_T2F + K2_ATTNF) * 4)   // 156992 B

// ---------------- device scratch ----------------
__device__ __align__(16) __half g_Wh[W_ELEMS];    // [d][cperm16]
__device__ __align__(16) __half g_Wl[W_ELEMS];
__device__ __align__(16) __half g_WTh[W_ELEMS];   // [c][dperm16]
__device__ __align__(16) __half g_WTl[W_ELEMS];
__device__ float g_T2p[KS1 * T2_STRIDE];          // 16 MB
__device__ __align__(16) __half g_CAh[MROWS * 256];  // [row][cperm16]
__device__ __align__(16) __half g_CAl[MROWS * 256];

// ---------------- helpers ----------------
__device__ __forceinline__ unsigned pk2(float a, float b) {
    __half2 h = __floats2half2_rn(a, b);
    return *reinterpret_cast<unsigned*>(&h);
}
__device__ __forceinline__ void mma_f16(float* c, unsigned a0, unsigned a1,
                                        unsigned a2, unsigned a3,
                                        unsigned b0, unsigned b1) {
    asm volatile(
        "mma.sync.aligned.m16n8k16.row.col.f32.f16.f16.f32 "
        "{%0,%1,%2,%3}, {%4,%5,%6,%7}, {%8,%9}, {%0,%1,%2,%3};"
        : "+f"(c[0]), "+f"(c[1]), "+f"(c[2]), "+f"(c[3])
        : "r"(a0), "r"(a1), "r"(a2), "r"(a3), "r"(b0), "r"(b1));
}
__device__ __forceinline__ unsigned smem_u32(const void* p) {
    unsigned a;
    asm("{ .reg .u64 t; cvta.to.shared.u64 t, %1; cvt.u32.u64 %0, t; }"
        : "=r"(a) : "l"(p));
    return a;
}
__device__ __forceinline__ void cpa16(unsigned dst, const void* src) {
    asm volatile("cp.async.cg.shared.global [%0], [%1], 16;"
                 :: "r"(dst), "l"(src));
}
#define CP_COMMIT() asm volatile("cp.async.commit_group;" ::: "memory")
#define CP_WAIT(N)  asm volatile("cp.async.wait_group %0;" :: "n"(N) : "memory")

__device__ __forceinline__ void split_g16(const float* v, __half* dh, __half* dl) {
    float h[16], l[16];
#pragma unroll
    for (int e = 0; e < 16; ++e) {
        h[e] = __half2float(__float2half_rn(v[e]));
        l[e] = v[e] - h[e];
    }
    *(uint4*)dh = make_uint4(pk2(h[0], h[1]), pk2(h[8], h[9]),
                             pk2(h[2], h[3]), pk2(h[10], h[11]));
    *(uint4*)(dh + 8) = make_uint4(pk2(h[4], h[5]), pk2(h[12], h[13]),
                                   pk2(h[6], h[7]), pk2(h[14], h[15]));
    *(uint4*)dl = make_uint4(pk2(l[0], l[1]), pk2(l[8], l[9]),
                             pk2(l[2], l[3]), pk2(l[10], l[11]));
    *(uint4*)(dl + 8) = make_uint4(pk2(l[4], l[5]), pk2(l[12], l[13]),
                                   pk2(l[6], l[7]), pk2(l[14], l[15]));
}

// ============================================================================
// k0b: split W -> fp16 native [d][cperm16] and transposed [c][dperm16]
// ============================================================================
__global__ __launch_bounds__(256) void k0b_split_W(const float* __restrict__ W) {
    __shared__ float tw[32 * 260];
    const int d0  = blockIdx.x * 32;
    const int tid = threadIdx.x;
    {
        int row = tid >> 3;
        int c0  = (tid & 7) * 32;
#pragma unroll
        for (int grp = 0; grp < 2; ++grp) {
            int cb = c0 + grp * 16;
            float v[16];
#pragma unroll
            for (int j = 0; j < 4; ++j) {
                float4 t = *(const float4*)(W + (d0 + row) * 256 + cb + 4 * j);
                v[4*j] = t.x; v[4*j+1] = t.y; v[4*j+2] = t.z; v[4*j+3] = t.w;
                *(float4*)(tw + row * 260 + cb + 4 * j) = t;
            }
            split_g16(v, g_Wh + (d0 + row) * 256 + cb,
                         g_Wl + (d0 + row) * 256 + cb);
        }
    }
    __syncthreads();
    {
        int c = tid;
#pragma unroll
        for (int g = 0; g < 2; ++g) {
            float v[16];
#pragma unroll
            for (int i = 0; i < 16; ++i)
                v[i] = tw[(g * 16 + i) * 260 + c];
            split_g16(v, g_WTh + (size_t)c * IDF_SZ + d0 + g * 16,
                         g_WTl + (size_t)c * IDF_SZ + d0 + g * 16);
        }
    }
}

// ============================================================================
// k1: T2 partials. 256 threads, M=64(row) x N=128(c), K=1024/block.
//   Grid (64 = 32mt x 2nt, 8 ks) = 512 CTAs. 8 warps (2m x 4n), warp 32x32.
//   3-stage ring, 1 sync/chunk, 3 CTAs/SM.
//   A: raw input LDG (threads 0-127: row tid>>1, half tid&1) -> split -> STS.
//   B: cp.async from pre-split g_WT{h,l}.
// ============================================================================
__global__ __launch_bounds__(256, 3) void k1_mma(const float* __restrict__ inp) {
    extern __shared__ char smc[];
    const int mt = blockIdx.x >> 1, nt = blockIdx.x & 1, ks = blockIdx.y;
    const int m0 = mt * 64, n0 = nt * 128, kg0 = ks * 1024;
    const int tid = threadIdx.x, wid = tid >> 5, lane = tid & 31;
    const int mw = wid & 1, nw = wid >> 1;          // 2m x 4n
    const int lr = lane >> 2, lc = lane & 3;
    const unsigned smb = smem_u32(smc);

    float acc[2][4][4];
#pragma unroll
    for (int i = 0; i < 2; ++i)
#pragma unroll
        for (int j = 0; j < 4; ++j)
#pragma unroll
            for (int e = 0; e < 4; ++e) acc[i][j][e] = 0.0f;

    // A loader: threads 0..127: row = tid>>1 (0..63), half = tid&1
    const int arow = (tid >> 1) & 63;
    const int ahalf = tid & 1;
    const int aR = m0 + arow;
    const int ab = aR >> 5, aq = aR & 31;

    auto load_A_regs = [&](int ch, float* xr) {
        if (tid < 128) {
            const int kg = kg0 + ch * 16;
            const int cl = kg >> 8, hw = (kg & 255) + ahalf * 4;
            const float* src = inp + (((ab * 32 + cl) * 32 + aq) << 8) + hw;
            float4 v0 = *(const float4*)(src);       // k: 4h+0..3
            float4 v1 = *(const float4*)(src + 8);   // k: 4h+8..11
            xr[0] = v0.x; xr[1] = v0.y; xr[2] = v0.z; xr[3] = v0.w;
            xr[4] = v1.x; xr[5] = v1.y; xr[6] = v1.z; xr[7] = v1.w;
        }
    };
    auto sts_A = [&](int st, const float* xr) {
        if (tid < 128) {
            float h[8], l[8];
#pragma unroll
            for (int e = 0; e < 8; ++e) {
                h[e] = __half2float(__float2half_rn(xr[e]));
                l[e] = xr[e] - h[e];
            }
            // sub layout: {x0,x1, x4,x5, x2,x3, x6,x7}
            char* base = smc + st * STG + ahalf * SUB64 + arow * 16;
            *(uint4*)(base) = make_uint4(pk2(h[0],h[1]), pk2(h[4],h[5]),
                                         pk2(h[2],h[3]), pk2(h[6],h[7]));
            *(uint4*)(base + ARR64) = make_uint4(pk2(l[0],l[1]), pk2(l[4],l[5]),
                                                 pk2(l[2],l[3]), pk2(l[6],l[7]));
        }
    };
    auto load_B = [&](int st, int ch) {
        const int kg = kg0 + ch * 16;
        const unsigned sb = smb + st * STG + 2 * ARR64;
#pragma unroll
        for (int it = 0; it < 2; ++it) {
            int idx = it * 256 + tid;            // 0..511
            int arr = idx >> 8, rem = idx & 255;
            int n = rem >> 1, sub = rem & 1;
            unsigned dst = sb + arr * ARR128 + sub * SUB128 + n * 16;
            const __half* src = (arr ? g_WTl : g_WTh)
                              + (size_t)(n0 + n) * IDF_SZ + kg + sub * 8;
            cpa16(dst, src);
        }
    };

    float xr[8];
    load_A_regs(0, xr);
    sts_A(0, xr);
    load_A_regs(1, xr);
    load_B(0, 0); CP_COMMIT();
    load_B(1, 1); CP_COMMIT();

    const int aoffA = (lc >> 1) * SUB64 + (lc & 1) * 8;
    const int aoffB = (lc >> 1) * SUB128 + (lc & 1) * 8;

    for (int ch = 0; ch < K1_NCH; ++ch) {
        const int st = ch % 3;
        CP_WAIT(1);
        __syncthreads();
        if (ch + 1 < K1_NCH) sts_A((ch + 1) % 3, xr);
        if (ch + 2 < K1_NCH) {
            load_A_regs(ch + 2, xr);
            load_B((ch + 2) % 3, ch + 2);
        }
        CP_COMMIT();

        const char* base = smc + st * STG;
        const char* pAh = base;
        const char* pAl = base + ARR64;
        const char* pBh = base + 2 * ARR64;
        const char* pBl = base + 2 * ARR64 + ARR128;

        uint2 bh[4], bl[4];
#pragma unroll
        for (int sn = 0; sn < 4; ++sn) {
            int nb = nw * 32 + sn * 8 + lr;
            bh[sn] = *(const uint2*)(pBh + aoffB + nb * 16);
            bl[sn] = *(const uint2*)(pBl + aoffB + nb * 16);
        }
        {
            uint2 alo[2], ahi[2];
#pragma unroll
            for (int sm = 0; sm < 2; ++sm) {
                int rb = mw * 32 + sm * 16 + lr;
                alo[sm] = *(const uint2*)(pAh + aoffA + rb * 16);
                ahi[sm] = *(const uint2*)(pAh + aoffA + (rb + 8) * 16);
            }
#pragma unroll
            for (int sm = 0; sm < 2; ++sm)
#pragma unroll
                for (int sn = 0; sn < 4; ++sn) {
                    mma_f16(acc[sm][sn], alo[sm].x, ahi[sm].x, alo[sm].y, ahi[sm].y,
                            bh[sn].x, bh[sn].y);
                    mma_f16(acc[sm][sn], alo[sm].x, ahi[sm].x, alo[sm].y, ahi[sm].y,
                            bl[sn].x, bl[sn].y);
                }
        }
        {
            uint2 alo[2], ahi[2];
#pragma unroll
            for (int sm = 0; sm < 2; ++sm) {
                int rb = mw * 32 + sm * 16 + lr;
                alo[sm] = *(const uint2*)(pAl + aoffA + rb * 16);
                ahi[sm] = *(const uint2*)(pAl + aoffA + (rb + 8) * 16);
            }
#pragma unroll
            for (int sm = 0; sm < 2; ++sm)
#pragma unroll
                for (int sn = 0; sn < 4; ++sn)
                    mma_f16(acc[sm][sn], alo[sm].x, ahi[sm].x, alo[sm].y, ahi[sm].y,
                            bh[sn].x, bh[sn].y);
        }
    }

    float* dst = g_T2p + (size_t)ks * T2_STRIDE;
#pragma unroll
    for (int sm = 0; sm < 2; ++sm) {
        int r = m0 + mw * 32 + sm * 16 + lr;
#pragma unroll
        for (int sn = 0; sn < 4; ++sn) {
            int c = n0 + nw * 32 + sn * 8 + 2 * lc;
            *(float2*)(dst + r * 256 + c) = make_float2(acc[sm][sn][0], acc[sm][sn][1]);
            *(float2*)(dst + (r + 8) * 256 + c) = make_float2(acc[sm][sn][2], acc[sm][sn][3]);
        }
    }
}

// ============================================================================
// k2 (2 blocks per b, 16 q-rows each, 256 threads): smem-staged ctx.
// ============================================================================
__global__ __launch_bounds__(256) void k2_attn(const float* __restrict__ ctx,
                                               float* __restrict__ outAttnT) {
    extern __shared__ float s2[];
    float* ctxs = s2;
    float* T2s  = s2 + K2_CTXF;
    float* attn = T2s + K2_T2F;

    const int b   = blockIdx.x >> 1;
    const int q0  = (blockIdx.x & 1) * 16;
    const int tid = threadIdx.x;

    {
        const float* cb = ctx + b * 32768;
#pragma unroll
        for (int i = 0; i < 32; ++i) {
            int idx = tid + i * 256;
            int c = idx >> 5, s4 = (idx & 31) * 4;
            float4 v = *(const float4*)(cb + c * 128 + s4);
            float* d = ctxs + c * CPAD + s4;
            d[0] = v.x; d[1] = v.y; d[2] = v.z; d[3] = v.w;
        }
    }
#pragma unroll
    for (int i = 0; i < 4; ++i) {
        int idx = tid + i * 256;
        int ql  = idx >> 6;
        int cc  = (idx & 63) * 4;
        const float* src = g_T2p + (b * 32 + q0 + ql) * 256 + cc;
        float4 s = *(const float4*)(src);
#pragma unroll
        for (int p = 1; p < KS1; ++p) {
            float4 t = *(const float4*)(src + (size_t)p * T2_STRIDE);
            s.x += t.x; s.y += t.y; s.z += t.z; s.w += t.w;
        }
        *(float4*)(T2s + ql * 256 + cc) = s;
    }
    __syncthreads();

    {
        const int s = tid & 127;
        const int g = tid >> 7;
        float acc[8];
#pragma unroll
        for (int j = 0; j < 8; ++j) acc[j] = 0.0f;
        const float* t2 = T2s + g * 8 * 256;
        for (int c = 0; c < 256; ++c) {
            float cv = ctxs[c * CPAD + s];
#pragma unroll
            for (int j = 0; j < 8; ++j)
                acc[j] += t2[j * 256 + c] * cv;
        }
#pragma unroll
        for (int j = 0; j < 8; ++j) attn[(g * 8 + j) * APAD2 + s] = acc[j];
    }
    __syncthreads();

    {
        const int warp = tid >> 5, lane = tid & 31;
#pragma unroll
        for (int r = 0; r < 2; ++r) {
            int q = warp * 2 + r;
            float v0 = attn[q * APAD2 + lane];
            float v1 = attn[q * APAD2 + lane + 32];
            float v2 = attn[q * APAD2 + lane + 64];
            float v3 = attn[q * APAD2 + lane + 96];
            float mx = fmaxf(fmaxf(v0, v1), fmaxf(v2, v3));
#pragma unroll
            for (int o = 16; o > 0; o >>= 1)
                mx = fmaxf(mx, __shfl_xor_sync(0xffffffffu, mx, o));
            float e0 = expf(v0 - mx), e1 = expf(v1 - mx);
            float e2 = expf(v2 - mx), e3 = expf(v3 - mx);
            float sm = e0 + e1 + e2 + e3;
#pragma unroll
            for (int o = 16; o > 0; o >>= 1)
                sm += __shfl_xor_sync(0xffffffffu, sm, o);
            float inv = 1.0f / sm;
            attn[q * APAD2 + lane]      = e0 * inv;
            attn[q * APAD2 + lane + 32] = e1 * inv;
            attn[q * APAD2 + lane + 64] = e2 * inv;
            attn[q * APAD2 + lane + 96] = e3 * inv;
        }
    }
    __syncthreads();

#pragma unroll
    for (int i = 0; i < 8; ++i) {
        int idx = tid + i * 256;
        int s = idx >> 4, ql = idx & 15;
        outAttnT[b * 4096 + s * 32 + q0 + ql] = attn[ql * APAD2 + s];
    }

    {
        const int c = tid;
        float a2[16];
#pragma unroll
        for (int j = 0; j < 16; ++j) a2[j] = 0.0f;
        const float* cr = ctxs + c * CPAD;
        for (int s = 0; s < 128; ++s) {
            float cv = cr[s];
#pragma unroll
            for (int j = 0; j < 16; ++j)
                a2[j] += attn[j * APAD2 + s] * cv;
        }
        int jj = c & 15;
        int cpos = (c & ~15) | ((jj & 1) | (((jj >> 1) & 3) << 2) | (((jj >> 3) & 1) << 1));
#pragma unroll
        for (int j = 0; j < 16; ++j) {
            __half h = __float2half_rn(a2[j]);
            float l = a2[j] - __half2float(h);
            int gi = (b * 32 + q0 + j) * 256 + cpos;
            g_CAh[gi] = h;
            g_CAl[gi] = __float2half_rn(l);
        }
    }
}

// ============================================================================
// k3: wc = W @ CA^T, fp16 3-pass.  M=64(d) x N=128(4b x 32q), K=256.
//   Grid (128 mt, 16 bg) = 2048 CTAs. 8 warps (2m x 4n), warp 32x32.
//   4-stage ring, 1 sync/chunk, 3 CTAs/SM.
// ============================================================================
__global__ __launch_bounds__(256, 3) void k3_mma(float* __restrict__ out0) {
    extern __shared__ char smc[];
    const int m0 = blockIdx.x * 64;
    const int b0 = blockIdx.y * 4;
    const int tid = threadIdx.x, wid = tid >> 5, lane = tid & 31;
    const int mw = wid & 1, nw = wid >> 1;          // 2m x 4n
    const int lr = lane >> 2, lc = lane & 3;
    const unsigned smb = smem_u32(smc);

    float acc[2][4][4];
#pragma unroll
    for (int i = 0; i < 2; ++i)
#pragma unroll
        for (int j = 0; j < 4; ++j)
#pragma unroll
            for (int e = 0; e < 4; ++e) acc[i][j][e] = 0.0f;

    auto load_stage = [&](int st, int ch) {
        const int kg = ch * 16;
        const unsigned sb = smb + st * STG;
        // W arrays: 64 rows x 2 subs x 2 arrays = 256 cpa16
        {
            int arr = tid >> 7, rem = tid & 127;
            int r = rem >> 1, sub = rem & 1;
            unsigned dst = sb + arr * ARR64 + sub * SUB64 + r * 16;
            const __half* src = (arr ? g_Wl : g_Wh)
                              + (size_t)(m0 + r) * 256 + kg + sub * 8;
            cpa16(dst, src);
        }
        // CA arrays: 128 rows x 2 subs x 2 arrays = 512 cpa16
#pragma unroll
        for (int it = 0; it < 2; ++it) {
            int idx = it * 256 + tid;
            int arr = idx >> 8, rem = idx & 255;
            int r = rem >> 1, sub = rem & 1;
            unsigned dst = sb + 2 * ARR64 + arr * ARR128 + sub * SUB128 + r * 16;
            const __half* src = (arr ? g_CAl : g_CAh)
                              + (size_t)(b0 * 32 + r) * 256 + kg + sub * 8;
            cpa16(dst, src);
        }
    };

    load_stage(0, 0); CP_COMMIT();
    load_stage(1, 1); CP_COMMIT();
    load_stage(2, 2); CP_COMMIT();

    const int aoffA = (lc >> 1) * SUB64 + (lc & 1) * 8;
    const int aoffB = (lc >> 1) * SUB128 + (lc & 1) * 8;

    for (int ch = 0; ch < 16; ++ch) {
        const int st = ch & 3;
        CP_WAIT(2);
        __syncthreads();
        if (ch + 3 < 16) load_stage((ch + 3) & 3, ch + 3);
        CP_COMMIT();

        const char* base = smc + st * STG;
        const char* pAh = base;
        const char* pAl = base + ARR64;
        const char* pBh = base + 2 * ARR64;
        const char* pBl = base + 2 * ARR64 + ARR128;

        uint2 bh[4], bl[4];
#pragma unroll
        for (int sn = 0; sn < 4; ++sn) {
            int nb = nw * 32 + sn * 8 + lr;
            bh[sn] = *(const uint2*)(pBh + aoffB + nb * 16);
            bl[sn] = *(const uint2*)(pBl + aoffB + nb * 16);
        }
        {
            uint2 alo[2], ahi[2];
#pragma unroll
            for (int sm = 0; sm < 2; ++sm) {
                int rb = mw * 32 + sm * 16 + lr;
                alo[sm] = *(const uint2*)(pAh + aoffA + rb * 16);
                ahi[sm] = *(const uint2*)(pAh + aoffA + (rb + 8) * 16);
            }
#pragma unroll
            for (int sm = 0; sm < 2; ++sm)
#pragma unroll
                for (int sn = 0; sn < 4; ++sn) {
                    mma_f16(acc[sm][sn], alo[sm].x, ahi[sm].x, alo[sm].y, ahi[sm].y,
                            bh[sn].x, bh[sn].y);
                    mma_f16(acc[sm][sn], alo[sm].x, ahi[sm].x, alo[sm].y, ahi[sm].y,
                            bl[sn].x, bl[sn].y);
                }
        }
        {
            uint2 alo[2], ahi[2];
#pragma unroll
            for (int sm = 0; sm < 2; ++sm) {
                int rb = mw * 32 + sm * 16 + lr;
                alo[sm] = *(const uint2*)(pAl + aoffA + rb * 16);
                ahi[sm] = *(const uint2*)(pAl + aoffA + (rb + 8) * 16);
            }
#pragma unroll
            for (int sm = 0; sm < 2; ++sm)
#pragma unroll
                for (int sn = 0; sn < 4; ++sn)
                    mma_f16(acc[sm][sn], alo[sm].x, ahi[sm].x, alo[sm].y, ahi[sm].y,
                            bh[sn].x, bh[sn].y);
        }
    }

#pragma unroll
    for (int sm = 0; sm < 2; ++sm) {
        int dbase = m0 + mw * 32 + sm * 16 + lr;
#pragma unroll
        for (int sn = 0; sn < 4; ++sn) {
            int n = nw * 32 + sn * 8 + 2 * lc;
            int b = b0 + (n >> 5);
            int q = n & 31;
#pragma unroll
            for (int hf = 0; hf < 2; ++hf) {
                int d   = dbase + 8 * hf;
                int c2i = (d >> 3) & 31;
                int q2  = d >> 8;
                float* o = out0 + ((b * 32 + c2i) * 32 + q2) * 256 + (d & 7) * 32 + q;
                *(float2*)o = make_float2(acc[sm][sn][2 * hf], acc[sm][sn][2 * hf + 1]);
            }
        }
    }
}

// ============================================================================
extern "C" void kernel_launch(void* const* d_in, const int* in_sizes, int n_in,
                              void* d_out, int out_size) {
    const float* inp = (const float*)d_in[0];
    const float* ctx = (const float*)d_in[1];
    const float* W   = (const float*)d_in[2];
    float* out = (float*)d_out;

    static int inited = 0;
    if (!inited) {
        cudaFuncSetAttribute(k1_mma, cudaFuncAttributeMaxDynamicSharedMemorySize, K1_SMEM);
        cudaFuncSetAttribute(k2_attn, cudaFuncAttributeMaxDynamicSharedMemorySize, K2_SMEM);
        cudaFuncSetAttribute(k3_mma, cudaFuncAttributeMaxDynamicSharedMemorySize, K3_SMEM);
        inited = 1;
    }

    k0b_split_W<<<IDF_SZ / 32, 256>>>(W);
    k1_mma<<<dim3(64, KS1), 256, K1_SMEM>>>(inp);
    k2_attn<<<B_SZ * 2, 256, K2_SMEM>>>(ctx, out + WC_ELEMS);
    k3_mma<<<dim3(128, 16), 256, K3_SMEM>>>(out);
}

// round 14
// speedup vs baseline: 1.1054x; 1.1054x over previous
#include <cuda_runtime.h>
#include <cuda_fp16.h>

// Problem:
//   input   [64, 32, 32, 16, 16] f32  -> A rows [b*32+q][d], d = cl*256+hw
//   context [64, 256, 128]       f32
//   W       [8192, 256]          f32
// Outputs: wc [64,32,32,16,16] f32 (16.7M) ; attnT [64,128,32] f32 (262K)
//
// fp16 2-split (h+l), 3 MMA passes (hh, hl, lh), m16n8k16.
// k-dim in 16-groups, chunk order {k0,k1,k8,k9|k2,k3,k10,k11|...}.
// R14: k3 goes BARRIER-FREE — fragments loaded directly from the
// pre-permuted global arrays with LDG.64 (W+CA fit in L2), no smem, no
// syncthreads, no cp.async. k1/k2 = R11-measured versions.

#define B_SZ   64
#define IDF_SZ 8192
#define WC_ELEMS (B_SZ * IDF_SZ * 32)      // 16777216
#define W_ELEMS  (IDF_SZ * 256)
#define KS1    8
#define MROWS  (B_SZ * 32)                 // 2048
#define T2_STRIDE (MROWS * 256)            // 524288

// A-type array (128 rows x 16 fp16): sub0 2048B | pad 64 | sub1 2048B
#define A_SUB  2112
#define A_ARR  4160
// B-type array (256 rows x 16 fp16)
#define B_SUB  4160
#define B_ARR  8256

#define K1_STAGEB (2 * A_ARR + 2 * B_ARR)  // 24832 B
#define K1_SMEM   (3 * K1_STAGEB)          // 74496 B
#define K1_NCH    64

#define CPAD  129
#define APAD2 133
#define K2_CTXF  (256 * CPAD)
#define K2_T2F   (16 * 256)
#define K2_ATTNF (16 * APAD2)
#define K2_SMEM  ((K2_CTXF + K2_T2F + K2_ATTNF) * 4)   // 156992 B

// ---------------- device scratch ----------------
__device__ __align__(16) __half g_Wh[W_ELEMS];    // [d][cperm16]
__device__ __align__(16) __half g_Wl[W_ELEMS];
__device__ __align__(16) __half g_WTh[W_ELEMS];   // [c][dperm16]
__device__ __align__(16) __half g_WTl[W_ELEMS];
__device__ float g_T2p[KS1 * T2_STRIDE];          // 16 MB
__device__ __align__(16) __half g_CAh[MROWS * 256];  // [row][cperm16]
__device__ __align__(16) __half g_CAl[MROWS * 256];

// ---------------- helpers ----------------
__device__ __forceinline__ unsigned pk2(float a, float b) {
    __half2 h = __floats2half2_rn(a, b);
    return *reinterpret_cast<unsigned*>(&h);
}
__device__ __forceinline__ void mma_f16(float* c, unsigned a0, unsigned a1,
                                        unsigned a2, unsigned a3,
                                        unsigned b0, unsigned b1) {
    asm volatile(
        "mma.sync.aligned.m16n8k16.row.col.f32.f16.f16.f32 "
        "{%0,%1,%2,%3}, {%4,%5,%6,%7}, {%8,%9}, {%0,%1,%2,%3};"
        : "+f"(c[0]), "+f"(c[1]), "+f"(c[2]), "+f"(c[3])
        : "r"(a0), "r"(a1), "r"(a2), "r"(a3), "r"(b0), "r"(b1));
}
__device__ __forceinline__ unsigned smem_u32(const void* p) {
    unsigned a;
    asm("{ .reg .u64 t; cvta.to.shared.u64 t, %1; cvt.u32.u64 %0, t; }"
        : "=r"(a) : "l"(p));
    return a;
}
__device__ __forceinline__ void cpa16(unsigned dst, const void* src) {
    asm volatile("cp.async.cg.shared.global [%0], [%1], 16;"
                 :: "r"(dst), "l"(src));
}
#define CP_COMMIT() asm volatile("cp.async.commit_group;" ::: "memory")
#define CP_WAIT(N)  asm volatile("cp.async.wait_group %0;" :: "n"(N) : "memory")

__device__ __forceinline__ void split_g16(const float* v, __half* dh, __half* dl) {
    float h[16], l[16];
#pragma unroll
    for (int e = 0; e < 16; ++e) {
        h[e] = __half2float(__float2half_rn(v[e]));
        l[e] = v[e] - h[e];
    }
    *(uint4*)dh = make_uint4(pk2(h[0], h[1]), pk2(h[8], h[9]),
                             pk2(h[2], h[3]), pk2(h[10], h[11]));
    *(uint4*)(dh + 8) = make_uint4(pk2(h[4], h[5]), pk2(h[12], h[13]),
                                   pk2(h[6], h[7]), pk2(h[14], h[15]));
    *(uint4*)dl = make_uint4(pk2(l[0], l[1]), pk2(l[8], l[9]),
                             pk2(l[2], l[3]), pk2(l[10], l[11]));
    *(uint4*)(dl + 8) = make_uint4(pk2(l[4], l[5]), pk2(l[12], l[13]),
                                   pk2(l[6], l[7]), pk2(l[14], l[15]));
}

// ============================================================================
// k0b: split W -> fp16 native [d][cperm16] and transposed [c][dperm16]
// ============================================================================
__global__ __launch_bounds__(256) void k0b_split_W(const float* __restrict__ W) {
    __shared__ float tw[32 * 260];
    const int d0  = blockIdx.x * 32;
    const int tid = threadIdx.x;
    {
        int row = tid >> 3;
        int c0  = (tid & 7) * 32;
#pragma unroll
        for (int grp = 0; grp < 2; ++grp) {
            int cb = c0 + grp * 16;
            float v[16];
#pragma unroll
            for (int j = 0; j < 4; ++j) {
                float4 t = *(const float4*)(W + (d0 + row) * 256 + cb + 4 * j);
                v[4*j] = t.x; v[4*j+1] = t.y; v[4*j+2] = t.z; v[4*j+3] = t.w;
                *(float4*)(tw + row * 260 + cb + 4 * j) = t;
            }
            split_g16(v, g_Wh + (d0 + row) * 256 + cb,
                         g_Wl + (d0 + row) * 256 + cb);
        }
    }
    __syncthreads();
    {
        int c = tid;
#pragma unroll
        for (int g = 0; g < 2; ++g) {
            float v[16];
#pragma unroll
            for (int i = 0; i < 16; ++i)
                v[i] = tw[(g * 16 + i) * 260 + c];
            split_g16(v, g_WTh + (size_t)c * IDF_SZ + d0 + g * 16,
                         g_WTl + (size_t)c * IDF_SZ + d0 + g * 16);
        }
    }
}

// ============================================================================
// k1: T2 partials. 512 threads, M=128(row) x N=256(c), K=1024/block.
//   Grid (16 mt, 8 ks). 16 warps (2m x 8n). 3-stage cp.async ring.  (R11)
// ============================================================================
__global__ __launch_bounds__(512, 1) void k1_mma(const float* __restrict__ inp) {
    extern __shared__ char smc[];
    const int mt = blockIdx.x, ks = blockIdx.y;
    const int m0 = mt * 128, kg0 = ks * 1024;
    const int tid = threadIdx.x, wid = tid >> 5, lane = tid & 31;
    const int mw = wid & 1, nw = wid >> 1;
    const int lr = lane >> 2, lc = lane & 3;
    const unsigned smb = smem_u32(smc);

    float acc[4][4][4];
#pragma unroll
    for (int i = 0; i < 4; ++i)
#pragma unroll
        for (int j = 0; j < 4; ++j)
#pragma unroll
            for (int e = 0; e < 4; ++e) acc[i][j][e] = 0.0f;

    const int arow = tid;
    const int aR = m0 + (arow & 127);
    const int ab = aR >> 5, aq = aR & 31;

    auto load_A_regs = [&](int ch, float* xr) {
        if (tid < 128) {
            const int kg = kg0 + ch * 16;
            const int cl = kg >> 8, hw = kg & 255;
            const float* src = inp + (((ab * 32 + cl) * 32 + aq) << 8) + hw;
#pragma unroll
            for (int j = 0; j < 4; ++j) {
                float4 t = *(const float4*)(src + 4 * j);
                xr[4*j] = t.x; xr[4*j+1] = t.y; xr[4*j+2] = t.z; xr[4*j+3] = t.w;
            }
        }
    };
    auto sts_A = [&](int st, const float* xr) {
        if (tid < 128) {
            char* base = smc + st * K1_STAGEB + arow * 16;
            float h[16], l[16];
#pragma unroll
            for (int e = 0; e < 16; ++e) {
                h[e] = __half2float(__float2half_rn(xr[e]));
                l[e] = xr[e] - h[e];
            }
            *(uint4*)(base) = make_uint4(pk2(h[0],h[1]), pk2(h[8],h[9]),
                                         pk2(h[2],h[3]), pk2(h[10],h[11]));
            *(uint4*)(base + A_SUB) = make_uint4(pk2(h[4],h[5]), pk2(h[12],h[13]),
                                                 pk2(h[6],h[7]), pk2(h[14],h[15]));
            *(uint4*)(base + A_ARR) = make_uint4(pk2(l[0],l[1]), pk2(l[8],l[9]),
                                                 pk2(l[2],l[3]), pk2(l[10],l[11]));
            *(uint4*)(base + A_ARR + A_SUB) = make_uint4(pk2(l[4],l[5]), pk2(l[12],l[13]),
                                                         pk2(l[6],l[7]), pk2(l[14],l[15]));
        }
    };
    auto load_B = [&](int st, int ch) {
        const int kg = kg0 + ch * 16;
        const unsigned sb = smb + st * K1_STAGEB + 2 * A_ARR;
#pragma unroll
        for (int it = 0; it < 2; ++it) {
            int idx = it * 512 + tid;
            int arr = idx >> 9, rem = idx & 511;
            int n = rem >> 1, sub = rem & 1;
            unsigned dst = sb + arr * B_ARR + sub * B_SUB + n * 16;
            const __half* src = (arr ? g_WTl : g_WTh) + (size_t)n * IDF_SZ + kg + sub * 8;
            cpa16(dst, src);
        }
    };

    float xr[16];
    load_A_regs(0, xr);
    sts_A(0, xr);
    load_A_regs(1, xr);
    load_B(0, 0); CP_COMMIT();
    load_B(1, 1); CP_COMMIT();

    const int aoff = (lc >> 1) * A_SUB + (lc & 1) * 8;
    const int boff = (lc >> 1) * B_SUB + (lc & 1) * 8;

    for (int ch = 0; ch < K1_NCH; ++ch) {
        const int st = ch % 3;
        CP_WAIT(1);
        __syncthreads();
        if (ch + 1 < K1_NCH) sts_A((ch + 1) % 3, xr);
        if (ch + 2 < K1_NCH) {
            load_A_regs(ch + 2, xr);
            load_B((ch + 2) % 3, ch + 2);
        }
        CP_COMMIT();

        const char* base = smc + st * K1_STAGEB;
        const char* pAh = base;
        const char* pAl = base + A_ARR;
        const char* pBh = base + 2 * A_ARR;
        const char* pBl = base + 2 * A_ARR + B_ARR;

        uint2 bh[4], bl[4];
#pragma unroll
        for (int sn = 0; sn < 4; ++sn) {
            int nb = nw * 32 + sn * 8 + lr;
            bh[sn] = *(const uint2*)(pBh + boff + nb * 16);
            bl[sn] = *(const uint2*)(pBl + boff + nb * 16);
        }
        {
            uint2 alo[4], ahi[4];
#pragma unroll
            for (int sm = 0; sm < 4; ++sm) {
                int rb = mw * 64 + sm * 16 + lr;
                alo[sm] = *(const uint2*)(pAh + aoff + rb * 16);
                ahi[sm] = *(const uint2*)(pAh + aoff + (rb + 8) * 16);
            }
#pragma unroll
            for (int sm = 0; sm < 4; ++sm)
#pragma unroll
                for (int sn = 0; sn < 4; ++sn) {
                    mma_f16(acc[sm][sn], alo[sm].x, ahi[sm].x, alo[sm].y, ahi[sm].y,
                            bh[sn].x, bh[sn].y);
                    mma_f16(acc[sm][sn], alo[sm].x, ahi[sm].x, alo[sm].y, ahi[sm].y,
                            bl[sn].x, bl[sn].y);
                }
        }
        {
            uint2 alo[4], ahi[4];
#pragma unroll
            for (int sm = 0; sm < 4; ++sm) {
                int rb = mw * 64 + sm * 16 + lr;
                alo[sm] = *(const uint2*)(pAl + aoff + rb * 16);
                ahi[sm] = *(const uint2*)(pAl + aoff + (rb + 8) * 16);
            }
#pragma unroll
            for (int sm = 0; sm < 4; ++sm)
#pragma unroll
                for (int sn = 0; sn < 4; ++sn)
                    mma_f16(acc[sm][sn], alo[sm].x, ahi[sm].x, alo[sm].y, ahi[sm].y,
                            bh[sn].x, bh[sn].y);
        }
        __syncthreads();
    }

    float* dst = g_T2p + (size_t)ks * T2_STRIDE;
#pragma unroll
    for (int sm = 0; sm < 4; ++sm) {
        int r = m0 + mw * 64 + sm * 16 + lr;
#pragma unroll
        for (int sn = 0; sn < 4; ++sn) {
            int c = nw * 32 + sn * 8 + 2 * lc;
            *(float2*)(dst + r * 256 + c) = make_float2(acc[sm][sn][0], acc[sm][sn][1]);
            *(float2*)(dst + (r + 8) * 256 + c) = make_float2(acc[sm][sn][2], acc[sm][sn][3]);
        }
    }
}

// ============================================================================
// k2 (2 blocks per b, 16 q-rows each, 256 threads): smem-staged ctx.  (R11)
// ============================================================================
__global__ __launch_bounds__(256) void k2_attn(const float* __restrict__ ctx,
                                               float* __restrict__ outAttnT) {
    extern __shared__ float s2[];
    float* ctxs = s2;
    float* T2s  = s2 + K2_CTXF;
    float* attn = T2s + K2_T2F;

    const int b   = blockIdx.x >> 1;
    const int q0  = (blockIdx.x & 1) * 16;
    const int tid = threadIdx.x;

    {
        const float* cb = ctx + b * 32768;
#pragma unroll
        for (int i = 0; i < 32; ++i) {
            int idx = tid + i * 256;
            int c = idx >> 5, s4 = (idx & 31) * 4;
            float4 v = *(const float4*)(cb + c * 128 + s4);
            float* d = ctxs + c * CPAD + s4;
            d[0] = v.x; d[1] = v.y; d[2] = v.z; d[3] = v.w;
        }
    }
#pragma unroll
    for (int i = 0; i < 4; ++i) {
        int idx = tid + i * 256;
        int ql  = idx >> 6;
        int cc  = (idx & 63) * 4;
        const float* src = g_T2p + (b * 32 + q0 + ql) * 256 + cc;
        float4 s = *(const float4*)(src);
#pragma unroll
        for (int p = 1; p < KS1; ++p) {
            float4 t = *(const float4*)(src + (size_t)p * T2_STRIDE);
            s.x += t.x; s.y += t.y; s.z += t.z; s.w += t.w;
        }
        *(float4*)(T2s + ql * 256 + cc) = s;
    }
    __syncthreads();

    {
        const int s = tid & 127;
        const int g = tid >> 7;
        float acc[8];
#pragma unroll
        for (int j = 0; j < 8; ++j) acc[j] = 0.0f;
        const float* t2 = T2s + g * 8 * 256;
        for (int c = 0; c < 256; ++c) {
            float cv = ctxs[c * CPAD + s];
#pragma unroll
            for (int j = 0; j < 8; ++j)
                acc[j] += t2[j * 256 + c] * cv;
        }
#pragma unroll
        for (int j = 0; j < 8; ++j) attn[(g * 8 + j) * APAD2 + s] = acc[j];
    }
    __syncthreads();

    {
        const int warp = tid >> 5, lane = tid & 31;
#pragma unroll
        for (int r = 0; r < 2; ++r) {
            int q = warp * 2 + r;
            float v0 = attn[q * APAD2 + lane];
            float v1 = attn[q * APAD2 + lane + 32];
            float v2 = attn[q * APAD2 + lane + 64];
            float v3 = attn[q * APAD2 + lane + 96];
            float mx = fmaxf(fmaxf(v0, v1), fmaxf(v2, v3));
#pragma unroll
            for (int o = 16; o > 0; o >>= 1)
                mx = fmaxf(mx, __shfl_xor_sync(0xffffffffu, mx, o));
            float e0 = expf(v0 - mx), e1 = expf(v1 - mx);
            float e2 = expf(v2 - mx), e3 = expf(v3 - mx);
            float sm = e0 + e1 + e2 + e3;
#pragma unroll
            for (int o = 16; o > 0; o >>= 1)
                sm += __shfl_xor_sync(0xffffffffu, sm, o);
            float inv = 1.0f / sm;
            attn[q * APAD2 + lane]      = e0 * inv;
            attn[q * APAD2 + lane + 32] = e1 * inv;
            attn[q * APAD2 + lane + 64] = e2 * inv;
            attn[q * APAD2 + lane + 96] = e3 * inv;
        }
    }
    __syncthreads();

#pragma unroll
    for (int i = 0; i < 8; ++i) {
        int idx = tid + i * 256;
        int s = idx >> 4, ql = idx & 15;
        outAttnT[b * 4096 + s * 32 + q0 + ql] = attn[ql * APAD2 + s];
    }

    {
        const int c = tid;
        float a2[16];
#pragma unroll
        for (int j = 0; j < 16; ++j) a2[j] = 0.0f;
        const float* cr = ctxs + c * CPAD;
        for (int s = 0; s < 128; ++s) {
            float cv = cr[s];
#pragma unroll
            for (int j = 0; j < 16; ++j)
                a2[j] += attn[j * APAD2 + s] * cv;
        }
        int jj = c & 15;
        int cpos = (c & ~15) | ((jj & 1) | (((jj >> 1) & 3) << 2) | (((jj >> 3) & 1) << 1));
#pragma unroll
        for (int j = 0; j < 16; ++j) {
            __half h = __float2half_rn(a2[j]);
            float l = a2[j] - __half2float(h);
            int gi = (b * 32 + q0 + j) * 256 + cpos;
            g_CAh[gi] = h;
            g_CAl[gi] = __float2half_rn(l);
        }
    }
}

// ============================================================================
// k3: wc = W @ CA^T, fp16 3-pass — BARRIER-FREE direct-LDG fragments.
//   M=128(d) x N=128(4b x 32q), K=256 (16 chunks). No smem, no syncthreads.
//   Fragments are LDG.64 from the pre-permuted global arrays (L2-resident:
//   W 8MB + CA 1MB). 8 warps (4m x 2n), warp 32x64, fully independent.
// ============================================================================
__global__ __launch_bounds__(256) void k3_mma(float* __restrict__ out0) {
    const int m0 = blockIdx.x * 128;
    const int b0 = blockIdx.y * 4;
    const int tid = threadIdx.x, wid = tid >> 5, lane = tid & 31;
    const int mw = wid & 3, nw = wid >> 2;
    const int lr = lane >> 2, lc = lane & 3;
    // element offset (halfs) inside a 16-group for this lane's frag pair
    const int goff = (lc >> 1) * 8 + (lc & 1) * 4;

    float acc[2][8][4];
#pragma unroll
    for (int i = 0; i < 2; ++i)
#pragma unroll
        for (int j = 0; j < 8; ++j)
#pragma unroll
            for (int e = 0; e < 4; ++e) acc[i][j][e] = 0.0f;

    // row bases (in halfs)
    const __half* bhBase = g_CAh + (size_t)(b0 * 32 + nw * 64 + lr) * 256 + goff;
    const __half* blBase = g_CAl + (size_t)(b0 * 32 + nw * 64 + lr) * 256 + goff;
    const __half* whBase = g_Wh + (size_t)(m0 + mw * 32 + lr) * 256 + goff;
    const __half* wlBase = g_Wl + (size_t)(m0 + mw * 32 + lr) * 256 + goff;

    for (int ch = 0; ch < 16; ++ch) {
        const int kg = ch * 16;
        // B fragments (h and l): 16 LDG.64, all independent
        uint2 bh[8], bl[8];
#pragma unroll
        for (int sn = 0; sn < 8; ++sn) {
            bh[sn] = *(const uint2*)(bhBase + (size_t)sn * 8 * 256 + kg);
            bl[sn] = *(const uint2*)(blBase + (size_t)sn * 8 * 256 + kg);
        }
        // A high fragments -> passes hh, hl
        {
            uint2 alo[2], ahi[2];
#pragma unroll
            for (int sm = 0; sm < 2; ++sm) {
                alo[sm] = *(const uint2*)(whBase + (size_t)(sm * 16) * 256 + kg);
                ahi[sm] = *(const uint2*)(whBase + (size_t)(sm * 16 + 8) * 256 + kg);
            }
#pragma unroll
            for (int sm = 0; sm < 2; ++sm)
#pragma unroll
                for (int sn = 0; sn < 8; ++sn) {
                    mma_f16(acc[sm][sn], alo[sm].x, ahi[sm].x, alo[sm].y, ahi[sm].y,
                            bh[sn].x, bh[sn].y);
                    mma_f16(acc[sm][sn], alo[sm].x, ahi[sm].x, alo[sm].y, ahi[sm].y,
                            bl[sn].x, bl[sn].y);
                }
        }
        // A low fragments -> pass lh
        {
            uint2 alo[2], ahi[2];
#pragma unroll
            for (int sm = 0; sm < 2; ++sm) {
                alo[sm] = *(const uint2*)(wlBase + (size_t)(sm * 16) * 256 + kg);
                ahi[sm] = *(const uint2*)(wlBase + (size_t)(sm * 16 + 8) * 256 + kg);
            }
#pragma unroll
            for (int sm = 0; sm < 2; ++sm)
#pragma unroll
                for (int sn = 0; sn < 8; ++sn)
                    mma_f16(acc[sm][sn], alo[sm].x, ahi[sm].x, alo[sm].y, ahi[sm].y,
                            bh[sn].x, bh[sn].y);
        }
    }

#pragma unroll
    for (int sm = 0; sm < 2; ++sm) {
        int dbase = m0 + mw * 32 + sm * 16 + lr;
#pragma unroll
        for (int sn = 0; sn < 8; ++sn) {
            int n = nw * 64 + sn * 8 + 2 * lc;
            int b = b0 + (n >> 5);
            int q = n & 31;
#pragma unroll
            for (int hf = 0; hf < 2; ++hf) {
                int d   = dbase + 8 * hf;
                int c2i = (d >> 3) & 31;
                int q2  = d >> 8;
                float* o = out0 + ((b * 32 + c2i) * 32 + q2) * 256 + (d & 7) * 32 + q;
                *(float2*)o = make_float2(acc[sm][sn][2 * hf], acc[sm][sn][2 * hf + 1]);
            }
        }
    }
}

// ============================================================================
extern "C" void kernel_launch(void* const* d_in, const int* in_sizes, int n_in,
                              void* d_out, int out_size) {
    const float* inp = (const float*)d_in[0];
    const float* ctx = (const float*)d_in[1];
    const float* W   = (const float*)d_in[2];
    float* out = (float*)d_out;

    static int inited = 0;
    if (!inited) {
        cudaFuncSetAttribute(k1_mma, cudaFuncAttributeMaxDynamicSharedMemorySize, K1_SMEM);
        cudaFuncSetAttribute(k2_attn, cudaFuncAttributeMaxDynamicSharedMemorySize, K2_SMEM);
        inited = 1;
    }

    k0b_split_W<<<IDF_SZ / 32, 256>>>(W);
    k1_mma<<<dim3(16, KS1), 512, K1_SMEM>>>(inp);
    k2_attn<<<B_SZ * 2, 256, K2_SMEM>>>(ctx, out + WC_ELEMS);
    k3_mma<<<dim3(64, 16), 256>>>(out);
}

// round 15
// speedup vs baseline: 1.2946x; 1.1711x over previous
#include <cuda_runtime.h>
#include <cuda_fp16.h>

// Problem:
//   input   [64, 32, 32, 16, 16] f32  -> A rows [b*32+q][d], d = cl*256+hw
//   context [64, 256, 128]       f32
//   W       [8192, 256]          f32
// Outputs: wc [64,32,32,16,16] f32 (16.7M) ; attnT [64,128,32] f32 (262K)
//
// fp16 2-split (h+l), 3 MMA passes (hh, hl, lh), m16n8k16.
// R15: k3 operands stored FRAGMENT-MAJOR in global memory — a warp's
// fragment for an (m16|n8, k16) tile is 512B/256B contiguous, so one
// LDG.128/LDG.64 delivers it with 4/2 L1 wavefronts (was 8 each).
// k3 stays barrier-free (no smem). k1/k2 unchanged (R11 versions).

#define B_SZ   64
#define IDF_SZ 8192
#define WC_ELEMS (B_SZ * IDF_SZ * 32)      // 16777216
#define W_ELEMS  (IDF_SZ * 256)
#define KS1    8
#define MROWS  (B_SZ * 32)                 // 2048
#define T2_STRIDE (MROWS * 256)            // 524288

// A-type array (128 rows x 16 fp16): sub0 2048B | pad 64 | sub1 2048B
#define A_SUB  2112
#define A_ARR  4160
// B-type array (256 rows x 16 fp16)
#define B_SUB  4160
#define B_ARR  8256

#define K1_STAGEB (2 * A_ARR + 2 * B_ARR)  // 24832 B
#define K1_SMEM   (3 * K1_STAGEB)          // 74496 B
#define K1_NCH    64

#define CPAD  129
#define APAD2 133
#define K2_CTXF  (256 * CPAD)
#define K2_T2F   (16 * 256)
#define K2_ATTNF (16 * APAD2)
#define K2_SMEM  ((K2_CTXF + K2_T2F + K2_ATTNF) * 4)   // 156992 B

// ---------------- device scratch ----------------
// k1 operands (smem path, chunk-ordered 16-groups):
__device__ __align__(16) __half g_WTh[W_ELEMS];   // [c][dperm16]
__device__ __align__(16) __half g_WTl[W_ELEMS];
// k3 operands, FRAGMENT-MAJOR:
//   W:  [mt(512)][kt(16)][lane(32)][8 halfs]  (m16k16 A-frag per lane = 16B)
//   CA: [nt(256)][kt(16)][lane(32)][4 halfs]  (n8k16  B-frag per lane = 8B)
__device__ __align__(16) __half g_W3h[W_ELEMS];
__device__ __align__(16) __half g_W3l[W_ELEMS];
__device__ __align__(16) __half g_CA3h[MROWS * 256];
__device__ __align__(16) __half g_CA3l[MROWS * 256];
__device__ float g_T2p[KS1 * T2_STRIDE];          // 16 MB

// ---------------- helpers ----------------
__device__ __forceinline__ unsigned pk2(float a, float b) {
    __half2 h = __floats2half2_rn(a, b);
    return *reinterpret_cast<unsigned*>(&h);
}
__device__ __forceinline__ void mma_f16(float* c, unsigned a0, unsigned a1,
                                        unsigned a2, unsigned a3,
                                        unsigned b0, unsigned b1) {
    asm volatile(
        "mma.sync.aligned.m16n8k16.row.col.f32.f16.f16.f32 "
        "{%0,%1,%2,%3}, {%4,%5,%6,%7}, {%8,%9}, {%0,%1,%2,%3};"
        : "+f"(c[0]), "+f"(c[1]), "+f"(c[2]), "+f"(c[3])
        : "r"(a0), "r"(a1), "r"(a2), "r"(a3), "r"(b0), "r"(b1));
}
__device__ __forceinline__ unsigned smem_u32(const void* p) {
    unsigned a;
    asm("{ .reg .u64 t; cvta.to.shared.u64 t, %1; cvt.u32.u64 %0, t; }"
        : "=r"(a) : "l"(p));
    return a;
}
__device__ __forceinline__ void cpa16(unsigned dst, const void* src) {
    asm volatile("cp.async.cg.shared.global [%0], [%1], 16;"
                 :: "r"(dst), "l"(src));
}
#define CP_COMMIT() asm volatile("cp.async.commit_group;" ::: "memory")
#define CP_WAIT(N)  asm volatile("cp.async.wait_group %0;" :: "n"(N) : "memory")

__device__ __forceinline__ void split_g16(const float* v, __half* dh, __half* dl) {
    float h[16], l[16];
#pragma unroll
    for (int e = 0; e < 16; ++e) {
        h[e] = __half2float(__float2half_rn(v[e]));
        l[e] = v[e] - h[e];
    }
    *(uint4*)dh = make_uint4(pk2(h[0], h[1]), pk2(h[8], h[9]),
                             pk2(h[2], h[3]), pk2(h[10], h[11]));
    *(uint4*)(dh + 8) = make_uint4(pk2(h[4], h[5]), pk2(h[12], h[13]),
                                   pk2(h[6], h[7]), pk2(h[14], h[15]));
    *(uint4*)dl = make_uint4(pk2(l[0], l[1]), pk2(l[8], l[9]),
                             pk2(l[2], l[3]), pk2(l[10], l[11]));
    *(uint4*)(dl + 8) = make_uint4(pk2(l[4], l[5]), pk2(l[12], l[13]),
                                   pk2(l[6], l[7]), pk2(l[14], l[15]));
}

// ============================================================================
// k0b: split W -> transposed chunk-ordered [c][dperm16] (k1) AND
//      fragment-major W (k3).
// ============================================================================
__global__ __launch_bounds__(256) void k0b_split_W(const float* __restrict__ W) {
    __shared__ float tw[32 * 260];
    const int d0  = blockIdx.x * 32;
    const int tid = threadIdx.x;
    // stage 32 x 256 tile
    {
        int row = tid >> 3;
        int c0  = (tid & 7) * 32;
#pragma unroll
        for (int j = 0; j < 8; ++j)
            *(float4*)(tw + row * 260 + c0 + 4 * j) =
                *(const float4*)(W + (d0 + row) * 256 + c0 + 4 * j);
    }
    __syncthreads();
    // fragment-major W (2 m-tiles per block)
    {
        int tile = tid >> 7;           // 0..1
        int lane = (tid >> 2) & 31;    // 0..31
        int ktq  = tid & 3;            // 0..3 -> 4 kt each
        int lr = lane >> 2, lc = lane & 3;
        int r0 = tile * 16 + lr, r1 = r0 + 8;
#pragma unroll
        for (int kk = 0; kk < 4; ++kk) {
            int kt = ktq * 4 + kk;
            int cb = kt * 16 + 2 * lc;
            float x[8] = { tw[r0 * 260 + cb],     tw[r0 * 260 + cb + 1],
                           tw[r0 * 260 + cb + 8], tw[r0 * 260 + cb + 9],
                           tw[r1 * 260 + cb],     tw[r1 * 260 + cb + 1],
                           tw[r1 * 260 + cb + 8], tw[r1 * 260 + cb + 9] };
            float h[8], l[8];
#pragma unroll
            for (int e = 0; e < 8; ++e) {
                h[e] = __half2float(__float2half_rn(x[e]));
                l[e] = x[e] - h[e];
            }
            size_t idx = (((size_t)((d0 >> 4) + tile) * 16 + kt) << 8) + lane * 8;
            // order: a0(2) a2(2) a1(2) a3(2)
            *(uint4*)(g_W3h + idx) = make_uint4(pk2(h[0], h[1]), pk2(h[2], h[3]),
                                                pk2(h[4], h[5]), pk2(h[6], h[7]));
            *(uint4*)(g_W3l + idx) = make_uint4(pk2(l[0], l[1]), pk2(l[2], l[3]),
                                                pk2(l[4], l[5]), pk2(l[6], l[7]));
        }
    }
    // transposed chunk-ordered for k1
    {
        int c = tid;
#pragma unroll
        for (int g = 0; g < 2; ++g) {
            float v[16];
#pragma unroll
            for (int i = 0; i < 16; ++i)
                v[i] = tw[(g * 16 + i) * 260 + c];
            split_g16(v, g_WTh + (size_t)c * IDF_SZ + d0 + g * 16,
                         g_WTl + (size_t)c * IDF_SZ + d0 + g * 16);
        }
    }
}

// ============================================================================
// k1: T2 partials. 512 threads, M=128(row) x N=256(c), K=1024/block.
//   Grid (16 mt, 8 ks). 16 warps (2m x 8n). 3-stage cp.async ring.  (R11)
// ============================================================================
__global__ __launch_bounds__(512, 1) void k1_mma(const float* __restrict__ inp) {
    extern __shared__ char smc[];
    const int mt = blockIdx.x, ks = blockIdx.y;
    const int m0 = mt * 128, kg0 = ks * 1024;
    const int tid = threadIdx.x, wid = tid >> 5, lane = tid & 31;
    const int mw = wid & 1, nw = wid >> 1;
    const int lr = lane >> 2, lc = lane & 3;
    const unsigned smb = smem_u32(smc);

    float acc[4][4][4];
#pragma unroll
    for (int i = 0; i < 4; ++i)
#pragma unroll
        for (int j = 0; j < 4; ++j)
#pragma unroll
            for (int e = 0; e < 4; ++e) acc[i][j][e] = 0.0f;

    const int arow = tid;
    const int aR = m0 + (arow & 127);
    const int ab = aR >> 5, aq = aR & 31;

    auto load_A_regs = [&](int ch, float* xr) {
        if (tid < 128) {
            const int kg = kg0 + ch * 16;
            const int cl = kg >> 8, hw = kg & 255;
            const float* src = inp + (((ab * 32 + cl) * 32 + aq) << 8) + hw;
#pragma unroll
            for (int j = 0; j < 4; ++j) {
                float4 t = *(const float4*)(src + 4 * j);
                xr[4*j] = t.x; xr[4*j+1] = t.y; xr[4*j+2] = t.z; xr[4*j+3] = t.w;
            }
        }
    };
    auto sts_A = [&](int st, const float* xr) {
        if (tid < 128) {
            char* base = smc + st * K1_STAGEB + arow * 16;
            float h[16], l[16];
#pragma unroll
            for (int e = 0; e < 16; ++e) {
                h[e] = __half2float(__float2half_rn(xr[e]));
                l[e] = xr[e] - h[e];
            }
            *(uint4*)(base) = make_uint4(pk2(h[0],h[1]), pk2(h[8],h[9]),
                                         pk2(h[2],h[3]), pk2(h[10],h[11]));
            *(uint4*)(base + A_SUB) = make_uint4(pk2(h[4],h[5]), pk2(h[12],h[13]),
                                                 pk2(h[6],h[7]), pk2(h[14],h[15]));
            *(uint4*)(base + A_ARR) = make_uint4(pk2(l[0],l[1]), pk2(l[8],l[9]),
                                                 pk2(l[2],l[3]), pk2(l[10],l[11]));
            *(uint4*)(base + A_ARR + A_SUB) = make_uint4(pk2(l[4],l[5]), pk2(l[12],l[13]),
                                                         pk2(l[6],l[7]), pk2(l[14],l[15]));
        }
    };
    auto load_B = [&](int st, int ch) {
        const int kg = kg0 + ch * 16;
        const unsigned sb = smb + st * K1_STAGEB + 2 * A_ARR;
#pragma unroll
        for (int it = 0; it < 2; ++it) {
            int idx = it * 512 + tid;
            int arr = idx >> 9, rem = idx & 511;
            int n = rem >> 1, sub = rem & 1;
            unsigned dst = sb + arr * B_ARR + sub * B_SUB + n * 16;
            const __half* src = (arr ? g_WTl : g_WTh) + (size_t)n * IDF_SZ + kg + sub * 8;
            cpa16(dst, src);
        }
    };

    float xr[16];
    load_A_regs(0, xr);
    sts_A(0, xr);
    load_A_regs(1, xr);
    load_B(0, 0); CP_COMMIT();
    load_B(1, 1); CP_COMMIT();

    const int aoff = (lc >> 1) * A_SUB + (lc & 1) * 8;
    const int boff = (lc >> 1) * B_SUB + (lc & 1) * 8;

    for (int ch = 0; ch < K1_NCH; ++ch) {
        const int st = ch % 3;
        CP_WAIT(1);
        __syncthreads();
        if (ch + 1 < K1_NCH) sts_A((ch + 1) % 3, xr);
        if (ch + 2 < K1_NCH) {
            load_A_regs(ch + 2, xr);
            load_B((ch + 2) % 3, ch + 2);
        }
        CP_COMMIT();

        const char* base = smc + st * K1_STAGEB;
        const char* pAh = base;
        const char* pAl = base + A_ARR;
        const char* pBh = base + 2 * A_ARR;
        const char* pBl = base + 2 * A_ARR + B_ARR;

        uint2 bh[4], bl[4];
#pragma unroll
        for (int sn = 0; sn < 4; ++sn) {
            int nb = nw * 32 + sn * 8 + lr;
            bh[sn] = *(const uint2*)(pBh + boff + nb * 16);
            bl[sn] = *(const uint2*)(pBl + boff + nb * 16);
        }
        {
            uint2 alo[4], ahi[4];
#pragma unroll
            for (int sm = 0; sm < 4; ++sm) {
                int rb = mw * 64 + sm * 16 + lr;
                alo[sm] = *(const uint2*)(pAh + aoff + rb * 16);
                ahi[sm] = *(const uint2*)(pAh + aoff + (rb + 8) * 16);
            }
#pragma unroll
            for (int sm = 0; sm < 4; ++sm)
#pragma unroll
                for (int sn = 0; sn < 4; ++sn) {
                    mma_f16(acc[sm][sn], alo[sm].x, ahi[sm].x, alo[sm].y, ahi[sm].y,
                            bh[sn].x, bh[sn].y);
                    mma_f16(acc[sm][sn], alo[sm].x, ahi[sm].x, alo[sm].y, ahi[sm].y,
                            bl[sn].x, bl[sn].y);
                }
        }
        {
            uint2 alo[4], ahi[4];
#pragma unroll
            for (int sm = 0; sm < 4; ++sm) {
                int rb = mw * 64 + sm * 16 + lr;
                alo[sm] = *(const uint2*)(pAl + aoff + rb * 16);
                ahi[sm] = *(const uint2*)(pAl + aoff + (rb + 8) * 16);
            }
#pragma unroll
            for (int sm = 0; sm < 4; ++sm)
#pragma unroll
                for (int sn = 0; sn < 4; ++sn)
                    mma_f16(acc[sm][sn], alo[sm].x, ahi[sm].x, alo[sm].y, ahi[sm].y,
                            bh[sn].x, bh[sn].y);
        }
        __syncthreads();
    }

    float* dst = g_T2p + (size_t)ks * T2_STRIDE;
#pragma unroll
    for (int sm = 0; sm < 4; ++sm) {
        int r = m0 + mw * 64 + sm * 16 + lr;
#pragma unroll
        for (int sn = 0; sn < 4; ++sn) {
            int c = nw * 32 + sn * 8 + 2 * lc;
            *(float2*)(dst + r * 256 + c) = make_float2(acc[sm][sn][0], acc[sm][sn][1]);
            *(float2*)(dst + (r + 8) * 256 + c) = make_float2(acc[sm][sn][2], acc[sm][sn][3]);
        }
    }
}

// ============================================================================
// k2 (2 blocks per b, 16 q-rows each, 256 threads): smem-staged ctx.
//   CA emitted FRAGMENT-MAJOR for k3.
// ============================================================================
__global__ __launch_bounds__(256) void k2_attn(const float* __restrict__ ctx,
                                               float* __restrict__ outAttnT) {
    extern __shared__ float s2[];
    float* ctxs = s2;
    float* T2s  = s2 + K2_CTXF;
    float* attn = T2s + K2_T2F;

    const int b   = blockIdx.x >> 1;
    const int q0  = (blockIdx.x & 1) * 16;
    const int tid = threadIdx.x;

    {
        const float* cb = ctx + b * 32768;
#pragma unroll
        for (int i = 0; i < 32; ++i) {
            int idx = tid + i * 256;
            int c = idx >> 5, s4 = (idx & 31) * 4;
            float4 v = *(const float4*)(cb + c * 128 + s4);
            float* d = ctxs + c * CPAD + s4;
            d[0] = v.x; d[1] = v.y; d[2] = v.z; d[3] = v.w;
        }
    }
#pragma unroll
    for (int i = 0; i < 4; ++i) {
        int idx = tid + i * 256;
        int ql  = idx >> 6;
        int cc  = (idx & 63) * 4;
        const float* src = g_T2p + (b * 32 + q0 + ql) * 256 + cc;
        float4 s = *(const float4*)(src);
#pragma unroll
        for (int p = 1; p < KS1; ++p) {
            float4 t = *(const float4*)(src + (size_t)p * T2_STRIDE);
            s.x += t.x; s.y += t.y; s.z += t.z; s.w += t.w;
        }
        *(float4*)(T2s + ql * 256 + cc) = s;
    }
    __syncthreads();

    {
        const int s = tid & 127;
        const int g = tid >> 7;
        float acc[8];
#pragma unroll
        for (int j = 0; j < 8; ++j) acc[j] = 0.0f;
        const float* t2 = T2s + g * 8 * 256;
        for (int c = 0; c < 256; ++c) {
            float cv = ctxs[c * CPAD + s];
#pragma unroll
            for (int j = 0; j < 8; ++j)
                acc[j] += t2[j * 256 + c] * cv;
        }
#pragma unroll
        for (int j = 0; j < 8; ++j) attn[(g * 8 + j) * APAD2 + s] = acc[j];
    }
    __syncthreads();

    {
        const int warp = tid >> 5, lane = tid & 31;
#pragma unroll
        for (int r = 0; r < 2; ++r) {
            int q = warp * 2 + r;
            float v0 = attn[q * APAD2 + lane];
            float v1 = attn[q * APAD2 + lane + 32];
            float v2 = attn[q * APAD2 + lane + 64];
            float v3 = attn[q * APAD2 + lane + 96];
            float mx = fmaxf(fmaxf(v0, v1), fmaxf(v2, v3));
#pragma unroll
            for (int o = 16; o > 0; o >>= 1)
                mx = fmaxf(mx, __shfl_xor_sync(0xffffffffu, mx, o));
            float e0 = expf(v0 - mx), e1 = expf(v1 - mx);
            float e2 = expf(v2 - mx), e3 = expf(v3 - mx);
            float sm = e0 + e1 + e2 + e3;
#pragma unroll
            for (int o = 16; o > 0; o >>= 1)
                sm += __shfl_xor_sync(0xffffffffu, sm, o);
            float inv = 1.0f / sm;
            attn[q * APAD2 + lane]      = e0 * inv;
            attn[q * APAD2 + lane + 32] = e1 * inv;
            attn[q * APAD2 + lane + 64] = e2 * inv;
            attn[q * APAD2 + lane + 96] = e3 * inv;
        }
    }
    __syncthreads();

#pragma unroll
    for (int i = 0; i < 8; ++i) {
        int idx = tid + i * 256;
        int s = idx >> 4, ql = idx & 15;
        outAttnT[b * 4096 + s * 32 + q0 + ql] = attn[ql * APAD2 + s];
    }

    // CA -> fragment-major: c is the k-dim; kt=c>>4, jj=c&15.
    //   B-frag lane = lr*4+lc with lr=n&7, lc=(jj>>1)&3;
    //   half position = (jj&1) | ((jj>>3)<<1).
    {
        const int c = tid;
        float a2[16];
#pragma unroll
        for (int j = 0; j < 16; ++j) a2[j] = 0.0f;
        const float* cr = ctxs + c * CPAD;
        for (int s = 0; s < 128; ++s) {
            float cv = cr[s];
#pragma unroll
            for (int j = 0; j < 16; ++j)
                a2[j] += attn[j * APAD2 + s] * cv;
        }
        const int kt  = c >> 4, jj = c & 15;
        const int lcb = (jj >> 1) & 3;
        const int pos = (jj & 1) | ((jj >> 3) << 1);
#pragma unroll
        for (int j = 0; j < 16; ++j) {
            int n  = b * 32 + q0 + j;
            int nt = n >> 3, lrb = n & 7;
            int lane = lrb * 4 + lcb;
            size_t idx = (((size_t)nt * 16 + kt) << 7) + lane * 4 + pos;
            __half h = __float2half_rn(a2[j]);
            float l = a2[j] - __half2float(h);
            g_CA3h[idx] = h;
            g_CA3l[idx] = __float2half_rn(l);
        }
    }
}

// ============================================================================
// k3: wc = W @ CA^T, fp16 3-pass — barrier-free, FRAGMENT-MAJOR LDG.
//   M=128(d) x N=128(4b x 32q), K=256 (16 chunks). 8 warps (4m x 2n).
//   A-frag: one LDG.128 (512B/warp contiguous); B-frag: one LDG.64 (256B).
// ============================================================================
__global__ __launch_bounds__(256) void k3_mma(float* __restrict__ out0) {
    const int m0 = blockIdx.x * 128;
    const int b0 = blockIdx.y * 4;
    const int tid = threadIdx.x, wid = tid >> 5, lane = tid & 31;
    const int mw = wid & 3, nw = wid >> 2;
    const int lr = lane >> 2, lc = lane & 3;

    float acc[2][8][4];
#pragma unroll
    for (int i = 0; i < 2; ++i)
#pragma unroll
        for (int j = 0; j < 8; ++j)
#pragma unroll
            for (int e = 0; e < 4; ++e) acc[i][j][e] = 0.0f;

    const int mtBase = (m0 >> 4) + mw * 2;   // + sm
    const int ntBase = b0 * 4 + nw * 8;      // + sn

    for (int ch = 0; ch < 16; ++ch) {
        // B fragments: one LDG.64 per (sn, array)
        uint2 bh[8], bl[8];
#pragma unroll
        for (int sn = 0; sn < 8; ++sn) {
            size_t bi = (((size_t)(ntBase + sn) * 16 + ch) << 7) + lane * 4;
            bh[sn] = *(const uint2*)(g_CA3h + bi);
            bl[sn] = *(const uint2*)(g_CA3l + bi);
        }
        // A high fragments: one LDG.128 per sm -> passes hh, hl
        {
            uint4 av[2];
#pragma unroll
            for (int sm = 0; sm < 2; ++sm) {
                size_t ai = (((size_t)(mtBase + sm) * 16 + ch) << 8) + lane * 8;
                av[sm] = *(const uint4*)(g_W3h + ai);
            }
            // packed order: {a0, a2, a1, a3} -> mma(a0=x, a1=z, a2=y, a3=w)
#pragma unroll
            for (int sm = 0; sm < 2; ++sm)
#pragma unroll
                for (int sn = 0; sn < 8; ++sn) {
                    mma_f16(acc[sm][sn], av[sm].x, av[sm].z, av[sm].y, av[sm].w,
                            bh[sn].x, bh[sn].y);
                    mma_f16(acc[sm][sn], av[sm].x, av[sm].z, av[sm].y, av[sm].w,
                            bl[sn].x, bl[sn].y);
                }
        }
        // A low fragments -> pass lh
        {
            uint4 av[2];
#pragma unroll
            for (int sm = 0; sm < 2; ++sm) {
                size_t ai = (((size_t)(mtBase + sm) * 16 + ch) << 8) + lane * 8;
                av[sm] = *(const uint4*)(g_W3l + ai);
            }
#pragma unroll
            for (int sm = 0; sm < 2; ++sm)
#pragma unroll
                for (int sn = 0; sn < 8; ++sn)
                    mma_f16(acc[sm][sn], av[sm].x, av[sm].z, av[sm].y, av[sm].w,
                            bh[sn].x, bh[sn].y);
        }
    }

#pragma unroll
    for (int sm = 0; sm < 2; ++sm) {
        int dbase = m0 + mw * 32 + sm * 16 + lr;
#pragma unroll
        for (int sn = 0; sn < 8; ++sn) {
            int n = nw * 64 + sn * 8 + 2 * lc;
            int b = b0 + (n >> 5);
            int q = n & 31;
#pragma unroll
            for (int hf = 0; hf < 2; ++hf) {
                int d   = dbase + 8 * hf;
                int c2i = (d >> 3) & 31;
                int q2  = d >> 8;
                float* o = out0 + ((b * 32 + c2i) * 32 + q2) * 256 + (d & 7) * 32 + q;
                *(float2*)o = make_float2(acc[sm][sn][2 * hf], acc[sm][sn][2 * hf + 1]);
            }
        }
    }
}

// ============================================================================
extern "C" void kernel_launch(void* const* d_in, const int* in_sizes, int n_in,
                              void* d_out, int out_size) {
    const float* inp = (const float*)d_in[0];
    const float* ctx = (const float*)d_in[1];
    const float* W   = (const float*)d_in[2];
    float* out = (float*)d_out;

    static int inited = 0;
    if (!inited) {
        cudaFuncSetAttribute(k1_mma, cudaFuncAttributeMaxDynamicSharedMemorySize, K1_SMEM);
        cudaFuncSetAttribute(k2_attn, cudaFuncAttributeMaxDynamicSharedMemorySize, K2_SMEM);
        inited = 1;
    }

    k0b_split_W<<<IDF_SZ / 32, 256>>>(W);
    k1_mma<<<dim3(16, KS1), 512, K1_SMEM>>>(inp);
    k2_attn<<<B_SZ * 2, 256, K2_SMEM>>>(ctx, out + WC_ELEMS);
    k3_mma<<<dim3(64, 16), 256>>>(out);
}

// round 16
// speedup vs baseline: 1.4522x; 1.1217x over previous
#include <cuda_runtime.h>
#include <cuda_fp16.h>

// Problem:
//   input   [64, 32, 32, 16, 16] f32  -> A rows [b*32+q][d], d = cl*256+hw
//   context [64, 256, 128]       f32
//   W       [8192, 256]          f32
// Outputs: wc [64,32,32,16,16] f32 (16.7M) ; attnT [64,128,32] f32 (262K)
//
// fp16 2-split, m16n8k16.  k1: 3 passes (softmax precision).
// k3: 2 passes (Wh*CAh + Wh*CAl; dropped Wl*CAh term ~1.4e-4 rel, R10-
// validated).  k3 barrier-free with FRAGMENT-MAJOR operands (R15 win).
// R16: k1 k-split 8 -> 9 (grid 144 ~ full chip, was 128/148 SMs).

#define B_SZ   64
#define IDF_SZ 8192
#define WC_ELEMS (B_SZ * IDF_SZ * 32)      // 16777216
#define W_ELEMS  (IDF_SZ * 256)
#define KS1    9
#define MROWS  (B_SZ * 32)                 // 2048
#define T2_STRIDE (MROWS * 256)            // 524288

// A-type array (128 rows x 16 fp16): sub0 2048B | pad 64 | sub1 2048B
#define A_SUB  2112
#define A_ARR  4160
// B-type array (256 rows x 16 fp16)
#define B_SUB  4160
#define B_ARR  8256

#define K1_STAGEB (2 * A_ARR + 2 * B_ARR)  // 24832 B
#define K1_SMEM   (3 * K1_STAGEB)          // 74496 B

#define CPAD  129
#define APAD2 133
#define K2_CTXF  (256 * CPAD)
#define K2_T2F   (16 * 256)
#define K2_ATTNF (16 * APAD2)
#define K2_SMEM  ((K2_CTXF + K2_T2F + K2_ATTNF) * 4)   // 156992 B

// ---------------- device scratch ----------------
// k1 operands (smem path, chunk-ordered 16-groups):
__device__ __align__(16) __half g_WTh[W_ELEMS];   // [c][dperm16]
__device__ __align__(16) __half g_WTl[W_ELEMS];
// k3 operands, FRAGMENT-MAJOR:
//   W:  [mt(512)][kt(16)][lane(32)][8 halfs]  (m16k16 A-frag per lane = 16B)
//   CA: [nt(256)][kt(16)][lane(32)][4 halfs]  (n8k16  B-frag per lane = 8B)
__device__ __align__(16) __half g_W3h[W_ELEMS];
__device__ __align__(16) __half g_CA3h[MROWS * 256];
__device__ __align__(16) __half g_CA3l[MROWS * 256];
__device__ float g_T2p[KS1 * T2_STRIDE];          // 18 MB

// ---------------- helpers ----------------
__device__ __forceinline__ unsigned pk2(float a, float b) {
    __half2 h = __floats2half2_rn(a, b);
    return *reinterpret_cast<unsigned*>(&h);
}
__device__ __forceinline__ void mma_f16(float* c, unsigned a0, unsigned a1,
                                        unsigned a2, unsigned a3,
                                        unsigned b0, unsigned b1) {
    asm volatile(
        "mma.sync.aligned.m16n8k16.row.col.f32.f16.f16.f32 "
        "{%0,%1,%2,%3}, {%4,%5,%6,%7}, {%8,%9}, {%0,%1,%2,%3};"
        : "+f"(c[0]), "+f"(c[1]), "+f"(c[2]), "+f"(c[3])
        : "r"(a0), "r"(a1), "r"(a2), "r"(a3), "r"(b0), "r"(b1));
}
__device__ __forceinline__ unsigned smem_u32(const void* p) {
    unsigned a;
    asm("{ .reg .u64 t; cvta.to.shared.u64 t, %1; cvt.u32.u64 %0, t; }"
        : "=r"(a) : "l"(p));
    return a;
}
__device__ __forceinline__ void cpa16(unsigned dst, const void* src) {
    asm volatile("cp.async.cg.shared.global [%0], [%1], 16;"
                 :: "r"(dst), "l"(src));
}
#define CP_COMMIT() asm volatile("cp.async.commit_group;" ::: "memory")
#define CP_WAIT(N)  asm volatile("cp.async.wait_group %0;" :: "n"(N) : "memory")

__device__ __forceinline__ void split_g16(const float* v, __half* dh, __half* dl) {
    float h[16], l[16];
#pragma unroll
    for (int e = 0; e < 16; ++e) {
        h[e] = __half2float(__float2half_rn(v[e]));
        l[e] = v[e] - h[e];
    }
    *(uint4*)dh = make_uint4(pk2(h[0], h[1]), pk2(h[8], h[9]),
                             pk2(h[2], h[3]), pk2(h[10], h[11]));
    *(uint4*)(dh + 8) = make_uint4(pk2(h[4], h[5]), pk2(h[12], h[13]),
                                   pk2(h[6], h[7]), pk2(h[14], h[15]));
    *(uint4*)dl = make_uint4(pk2(l[0], l[1]), pk2(l[8], l[9]),
                             pk2(l[2], l[3]), pk2(l[10], l[11]));
    *(uint4*)(dl + 8) = make_uint4(pk2(l[4], l[5]), pk2(l[12], l[13]),
                                   pk2(l[6], l[7]), pk2(l[14], l[15]));
}

// ============================================================================
// k0b: split W -> transposed chunk-ordered [c][dperm16] (k1) AND
//      fragment-major W-high (k3, 2-pass: no W-low needed).
// ============================================================================
__global__ __launch_bounds__(256) void k0b_split_W(const float* __restrict__ W) {
    __shared__ float tw[32 * 260];
    const int d0  = blockIdx.x * 32;
    const int tid = threadIdx.x;
    // stage 32 x 256 tile
    {
        int row = tid >> 3;
        int c0  = (tid & 7) * 32;
#pragma unroll
        for (int j = 0; j < 8; ++j)
            *(float4*)(tw + row * 260 + c0 + 4 * j) =
                *(const float4*)(W + (d0 + row) * 256 + c0 + 4 * j);
    }
    __syncthreads();
    // fragment-major W-high (2 m-tiles per block)
    {
        int tile = tid >> 7;           // 0..1
        int lane = (tid >> 2) & 31;    // 0..31
        int ktq  = tid & 3;            // 0..3 -> 4 kt each
        int lr = lane >> 2, lc = lane & 3;
        int r0 = tile * 16 + lr, r1 = r0 + 8;
#pragma unroll
        for (int kk = 0; kk < 4; ++kk) {
            int kt = ktq * 4 + kk;
            int cb = kt * 16 + 2 * lc;
            float x[8] = { tw[r0 * 260 + cb],     tw[r0 * 260 + cb + 1],
                           tw[r0 * 260 + cb + 8], tw[r0 * 260 + cb + 9],
                           tw[r1 * 260 + cb],     tw[r1 * 260 + cb + 1],
                           tw[r1 * 260 + cb + 8], tw[r1 * 260 + cb + 9] };
            float h[8];
#pragma unroll
            for (int e = 0; e < 8; ++e)
                h[e] = __half2float(__float2half_rn(x[e]));
            size_t idx = (((size_t)((d0 >> 4) + tile) * 16 + kt) << 8) + lane * 8;
            *(uint4*)(g_W3h + idx) = make_uint4(pk2(h[0], h[1]), pk2(h[2], h[3]),
                                                pk2(h[4], h[5]), pk2(h[6], h[7]));
        }
    }
    // transposed chunk-ordered for k1
    {
        int c = tid;
#pragma unroll
        for (int g = 0; g < 2; ++g) {
            float v[16];
#pragma unroll
            for (int i = 0; i < 16; ++i)
                v[i] = tw[(g * 16 + i) * 260 + c];
            split_g16(v, g_WTh + (size_t)c * IDF_SZ + d0 + g * 16,
                         g_WTl + (size_t)c * IDF_SZ + d0 + g * 16);
        }
    }
}

// ============================================================================
// k1: T2 partials. 512 threads, M=128(row) x N=256(c).
//   Grid (16 mt, 9 ks) = 144 CTAs (full chip). Uneven k-split: ks<8 get 57
//   chunks, ks=8 gets 56 (512 chunks total). 3-stage cp.async ring.
// ============================================================================
__global__ __launch_bounds__(512, 1) void k1_mma(const float* __restrict__ inp) {
    extern __shared__ char smc[];
    const int mt = blockIdx.x, ks = blockIdx.y;
    const int m0 = mt * 128;
    const int chbeg = ks * 56 + min(ks, 8);
    const int nch   = 56 + (ks < 8 ? 1 : 0);
    const int tid = threadIdx.x, wid = tid >> 5, lane = tid & 31;
    const int mw = wid & 1, nw = wid >> 1;
    const int lr = lane >> 2, lc = lane & 3;
    const unsigned smb = smem_u32(smc);

    float acc[4][4][4];
#pragma unroll
    for (int i = 0; i < 4; ++i)
#pragma unroll
        for (int j = 0; j < 4; ++j)
#pragma unroll
            for (int e = 0; e < 4; ++e) acc[i][j][e] = 0.0f;

    const int arow = tid;
    const int aR = m0 + (arow & 127);
    const int ab = aR >> 5, aq = aR & 31;

    auto load_A_regs = [&](int ch, float* xr) {
        if (tid < 128) {
            const int kg = (chbeg + ch) * 16;
            const int cl = kg >> 8, hw = kg & 255;
            const float* src = inp + (((ab * 32 + cl) * 32 + aq) << 8) + hw;
#pragma unroll
            for (int j = 0; j < 4; ++j) {
                float4 t = *(const float4*)(src + 4 * j);
                xr[4*j] = t.x; xr[4*j+1] = t.y; xr[4*j+2] = t.z; xr[4*j+3] = t.w;
            }
        }
    };
    auto sts_A = [&](int st, const float* xr) {
        if (tid < 128) {
            char* base = smc + st * K1_STAGEB + arow * 16;
            float h[16], l[16];
#pragma unroll
            for (int e = 0; e < 16; ++e) {
                h[e] = __half2float(__float2half_rn(xr[e]));
                l[e] = xr[e] - h[e];
            }
            *(uint4*)(base) = make_uint4(pk2(h[0],h[1]), pk2(h[8],h[9]),
                                         pk2(h[2],h[3]), pk2(h[10],h[11]));
            *(uint4*)(base + A_SUB) = make_uint4(pk2(h[4],h[5]), pk2(h[12],h[13]),
                                                 pk2(h[6],h[7]), pk2(h[14],h[15]));
            *(uint4*)(base + A_ARR) = make_uint4(pk2(l[0],l[1]), pk2(l[8],l[9]),
                                                 pk2(l[2],l[3]), pk2(l[10],l[11]));
            *(uint4*)(base + A_ARR + A_SUB) = make_uint4(pk2(l[4],l[5]), pk2(l[12],l[13]),
                                                         pk2(l[6],l[7]), pk2(l[14],l[15]));
        }
    };
    auto load_B = [&](int st, int ch) {
        const int kg = (chbeg + ch) * 16;
        const unsigned sb = smb + st * K1_STAGEB + 2 * A_ARR;
#pragma unroll
        for (int it = 0; it < 2; ++it) {
            int idx = it * 512 + tid;
            int arr = idx >> 9, rem = idx & 511;
            int n = rem >> 1, sub = rem & 1;
            unsigned dst = sb + arr * B_ARR + sub * B_SUB + n * 16;
            const __half* src = (arr ? g_WTl : g_WTh) + (size_t)n * IDF_SZ + kg + sub * 8;
            cpa16(dst, src);
        }
    };

    float xr[16];
    load_A_regs(0, xr);
    sts_A(0, xr);
    load_A_regs(1, xr);
    load_B(0, 0); CP_COMMIT();
    load_B(1, 1); CP_COMMIT();

    const int aoff = (lc >> 1) * A_SUB + (lc & 1) * 8;
    const int boff = (lc >> 1) * B_SUB + (lc & 1) * 8;

    for (int ch = 0; ch < nch; ++ch) {
        const int st = ch % 3;
        CP_WAIT(1);
        __syncthreads();
        if (ch + 1 < nch) sts_A((ch + 1) % 3, xr);
        if (ch + 2 < nch) {
            load_A_regs(ch + 2, xr);
            load_B((ch + 2) % 3, ch + 2);
        }
        CP_COMMIT();

        const char* base = smc + st * K1_STAGEB;
        const char* pAh = base;
        const char* pAl = base + A_ARR;
        const char* pBh = base + 2 * A_ARR;
        const char* pBl = base + 2 * A_ARR + B_ARR;

        uint2 bh[4], bl[4];
#pragma unroll
        for (int sn = 0; sn < 4; ++sn) {
            int nb = nw * 32 + sn * 8 + lr;
            bh[sn] = *(const uint2*)(pBh + boff + nb * 16);
            bl[sn] = *(const uint2*)(pBl + boff + nb * 16);
        }
        {
            uint2 alo[4], ahi[4];
#pragma unroll
            for (int sm = 0; sm < 4; ++sm) {
                int rb = mw * 64 + sm * 16 + lr;
                alo[sm] = *(const uint2*)(pAh + aoff + rb * 16);
                ahi[sm] = *(const uint2*)(pAh + aoff + (rb + 8) * 16);
            }
#pragma unroll
            for (int sm = 0; sm < 4; ++sm)
#pragma unroll
                for (int sn = 0; sn < 4; ++sn) {
                    mma_f16(acc[sm][sn], alo[sm].x, ahi[sm].x, alo[sm].y, ahi[sm].y,
                            bh[sn].x, bh[sn].y);
                    mma_f16(acc[sm][sn], alo[sm].x, ahi[sm].x, alo[sm].y, ahi[sm].y,
                            bl[sn].x, bl[sn].y);
                }
        }
        {
            uint2 alo[4], ahi[4];
#pragma unroll
            for (int sm = 0; sm < 4; ++sm) {
                int rb = mw * 64 + sm * 16 + lr;
                alo[sm] = *(const uint2*)(pAl + aoff + rb * 16);
                ahi[sm] = *(const uint2*)(pAl + aoff + (rb + 8) * 16);
            }
#pragma unroll
            for (int sm = 0; sm < 4; ++sm)
#pragma unroll
                for (int sn = 0; sn < 4; ++sn)
                    mma_f16(acc[sm][sn], alo[sm].x, ahi[sm].x, alo[sm].y, ahi[sm].y,
                            bh[sn].x, bh[sn].y);
        }
        __syncthreads();
    }

    float* dst = g_T2p + (size_t)ks * T2_STRIDE;
#pragma unroll
    for (int sm = 0; sm < 4; ++sm) {
        int r = m0 + mw * 64 + sm * 16 + lr;
#pragma unroll
        for (int sn = 0; sn < 4; ++sn) {
            int c = nw * 32 + sn * 8 + 2 * lc;
            *(float2*)(dst + r * 256 + c) = make_float2(acc[sm][sn][0], acc[sm][sn][1]);
            *(float2*)(dst + (r + 8) * 256 + c) = make_float2(acc[sm][sn][2], acc[sm][sn][3]);
        }
    }
}

// ============================================================================
// k2 (2 blocks per b, 16 q-rows each, 256 threads): smem-staged ctx.
//   Reduces 9 partials; CA emitted FRAGMENT-MAJOR for k3.
// ============================================================================
__global__ __launch_bounds__(256) void k2_attn(const float* __restrict__ ctx,
                                               float* __restrict__ outAttnT) {
    extern __shared__ float s2[];
    float* ctxs = s2;
    float* T2s  = s2 + K2_CTXF;
    float* attn = T2s + K2_T2F;

    const int b   = blockIdx.x >> 1;
    const int q0  = (blockIdx.x & 1) * 16;
    const int tid = threadIdx.x;

    {
        const float* cb = ctx + b * 32768;
#pragma unroll
        for (int i = 0; i < 32; ++i) {
            int idx = tid + i * 256;
            int c = idx >> 5, s4 = (idx & 31) * 4;
            float4 v = *(const float4*)(cb + c * 128 + s4);
            float* d = ctxs + c * CPAD + s4;
            d[0] = v.x; d[1] = v.y; d[2] = v.z; d[3] = v.w;
        }
    }
#pragma unroll
    for (int i = 0; i < 4; ++i) {
        int idx = tid + i * 256;
        int ql  = idx >> 6;
        int cc  = (idx & 63) * 4;
        const float* src = g_T2p + (b * 32 + q0 + ql) * 256 + cc;
        float4 s = *(const float4*)(src);
#pragma unroll
        for (int p = 1; p < KS1; ++p) {
            float4 t = *(const float4*)(src + (size_t)p * T2_STRIDE);
            s.x += t.x; s.y += t.y; s.z += t.z; s.w += t.w;
        }
        *(float4*)(T2s + ql * 256 + cc) = s;
    }
    __syncthreads();

    {
        const int s = tid & 127;
        const int g = tid >> 7;
        float acc[8];
#pragma unroll
        for (int j = 0; j < 8; ++j) acc[j] = 0.0f;
        const float* t2 = T2s + g * 8 * 256;
        for (int c = 0; c < 256; ++c) {
            float cv = ctxs[c * CPAD + s];
#pragma unroll
            for (int j = 0; j < 8; ++j)
                acc[j] += t2[j * 256 + c] * cv;
        }
#pragma unroll
        for (int j = 0; j < 8; ++j) attn[(g * 8 + j) * APAD2 + s] = acc[j];
    }
    __syncthreads();

    {
        const int warp = tid >> 5, lane = tid & 31;
#pragma unroll
        for (int r = 0; r < 2; ++r) {
            int q = warp * 2 + r;
            float v0 = attn[q * APAD2 + lane];
            float v1 = attn[q * APAD2 + lane + 32];
            float v2 = attn[q * APAD2 + lane + 64];
            float v3 = attn[q * APAD2 + lane + 96];
            float mx = fmaxf(fmaxf(v0, v1), fmaxf(v2, v3));
#pragma unroll
            for (int o = 16; o > 0; o >>= 1)
                mx = fmaxf(mx, __shfl_xor_sync(0xffffffffu, mx, o));
            float e0 = expf(v0 - mx), e1 = expf(v1 - mx);
            float e2 = expf(v2 - mx), e3 = expf(v3 - mx);
            float sm = e0 + e1 + e2 + e3;
#pragma unroll
            for (int o = 16; o > 0; o >>= 1)
                sm += __shfl_xor_sync(0xffffffffu, sm, o);
            float inv = 1.0f / sm;
            attn[q * APAD2 + lane]      = e0 * inv;
            attn[q * APAD2 + lane + 32] = e1 * inv;
            attn[q * APAD2 + lane + 64] = e2 * inv;
            attn[q * APAD2 + lane + 96] = e3 * inv;
        }
    }
    __syncthreads();

#pragma unroll
    for (int i = 0; i < 8; ++i) {
        int idx = tid + i * 256;
        int s = idx >> 4, ql = idx & 15;
        outAttnT[b * 4096 + s * 32 + q0 + ql] = attn[ql * APAD2 + s];
    }

    // CA -> fragment-major: c is the k-dim; kt=c>>4, jj=c&15.
    {
        const int c = tid;
        float a2[16];
#pragma unroll
        for (int j = 0; j < 16; ++j) a2[j] = 0.0f;
        const float* cr = ctxs + c * CPAD;
        for (int s = 0; s < 128; ++s) {
            float cv = cr[s];
#pragma unroll
            for (int j = 0; j < 16; ++j)
                a2[j] += attn[j * APAD2 + s] * cv;
        }
        const int kt  = c >> 4, jj = c & 15;
        const int lcb = (jj >> 1) & 3;
        const int pos = (jj & 1) | ((jj >> 3) << 1);
#pragma unroll
        for (int j = 0; j < 16; ++j) {
            int n  = b * 32 + q0 + j;
            int nt = n >> 3, lrb = n & 7;
            int lane = lrb * 4 + lcb;
            size_t idx = (((size_t)nt * 16 + kt) << 7) + lane * 4 + pos;
            __half h = __float2half_rn(a2[j]);
            float l = a2[j] - __half2float(h);
            g_CA3h[idx] = h;
            g_CA3l[idx] = __float2half_rn(l);
        }
    }
}

// ============================================================================
// k3: wc = Wh @ (CAh + CAl)^T, fp16 2-pass — barrier-free, frag-major LDG.
//   M=128(d) x N=128(4b x 32q), K=256 (16 chunks). 8 warps (4m x 2n).
// ============================================================================
__global__ __launch_bounds__(256) void k3_mma(float* __restrict__ out0) {
    const int m0 = blockIdx.x * 128;
    const int b0 = blockIdx.y * 4;
    const int tid = threadIdx.x, wid = tid >> 5, lane = tid & 31;
    const int mw = wid & 3, nw = wid >> 2;
    const int lr = lane >> 2, lc = lane & 3;

    float acc[2][8][4];
#pragma unroll
    for (int i = 0; i < 2; ++i)
#pragma unroll
        for (int j = 0; j < 8; ++j)
#pragma unroll
            for (int e = 0; e < 4; ++e) acc[i][j][e] = 0.0f;

    const int mtBase = (m0 >> 4) + mw * 2;   // + sm
    const int ntBase = b0 * 4 + nw * 8;      // + sn

    for (int ch = 0; ch < 16; ++ch) {
        uint2 bh[8], bl[8];
#pragma unroll
        for (int sn = 0; sn < 8; ++sn) {
            size_t bi = (((size_t)(ntBase + sn) * 16 + ch) << 7) + lane * 4;
            bh[sn] = *(const uint2*)(g_CA3h + bi);
            bl[sn] = *(const uint2*)(g_CA3l + bi);
        }
        uint4 av[2];
#pragma unroll
        for (int sm = 0; sm < 2; ++sm) {
            size_t ai = (((size_t)(mtBase + sm) * 16 + ch) << 8) + lane * 8;
            av[sm] = *(const uint4*)(g_W3h + ai);
        }
        // packed order: {a0, a2, a1, a3} -> mma(a0=x, a1=z, a2=y, a3=w)
#pragma unroll
        for (int sm = 0; sm < 2; ++sm)
#pragma unroll
            for (int sn = 0; sn < 8; ++sn) {
                mma_f16(acc[sm][sn], av[sm].x, av[sm].z, av[sm].y, av[sm].w,
                        bh[sn].x, bh[sn].y);
                mma_f16(acc[sm][sn], av[sm].x, av[sm].z, av[sm].y, av[sm].w,
                        bl[sn].x, bl[sn].y);
            }
    }

#pragma unroll
    for (int sm = 0; sm < 2; ++sm) {
        int dbase = m0 + mw * 32 + sm * 16 + lr;
#pragma unroll
        for (int sn = 0; sn < 8; ++sn) {
            int n = nw * 64 + sn * 8 + 2 * lc;
            int b = b0 + (n >> 5);
            int q = n & 31;
#pragma unroll
            for (int hf = 0; hf < 2; ++hf) {
                int d   = dbase + 8 * hf;
                int c2i = (d >> 3) & 31;
                int q2  = d >> 8;
                float* o = out0 + ((b * 32 + c2i) * 32 + q2) * 256 + (d & 7) * 32 + q;
                *(float2*)o = make_float2(acc[sm][sn][2 * hf], acc[sm][sn][2 * hf + 1]);
            }
        }
    }
}

// ============================================================================
extern "C" void kernel_launch(void* const* d_in, const int* in_sizes, int n_in,
                              void* d_out, int out_size) {
    const float* inp = (const float*)d_in[0];
    const float* ctx = (const float*)d_in[1];
    const float* W   = (const float*)d_in[2];
    float* out = (float*)d_out;

    static int inited = 0;
    if (!inited) {
        cudaFuncSetAttribute(k1_mma, cudaFuncAttributeMaxDynamicSharedMemorySize, K1_SMEM);
        cudaFuncSetAttribute(k2_attn, cudaFuncAttributeMaxDynamicSharedMemorySize, K2_SMEM);
        inited = 1;
    }

    k0b_split_W<<<IDF_SZ / 32, 256>>>(W);
    k1_mma<<<dim3(16, KS1), 512, K1_SMEM>>>(inp);
    k2_attn<<<B_SZ * 2, 256, K2_SMEM>>>(ctx, out + WC_ELEMS);
    k3_mma<<<dim3(64, 16), 256>>>(out);
}